// round 9
// baseline (speedup 1.0000x reference)
#include <cuda_runtime.h>
#include <cuda_bf16.h>

// Problem constants
#define BATCH 256
#define TT    1024
#define INP   128
#define LAT   64
#define HID   128
#define OUTD  32

// ---------- f32x2 helpers ----------
__device__ __forceinline__ void fma2(unsigned long long& acc,
                                     unsigned long long a,
                                     unsigned long long b) {
    asm("fma.rn.f32x2 %0, %1, %2, %0;" : "+l"(acc) : "l"(a), "l"(b));
}
__device__ __forceinline__ float psum2(unsigned long long v) {
    float lo, hi;
    asm("mov.b64 {%0,%1}, %2;" : "=f"(lo), "=f"(hi) : "l"(v));
    return lo + hi;
}
__device__ __forceinline__ void gbar(int id) {
    asm volatile("bar.sync %0, 256;" :: "r"(id) : "memory");
}

// =====================================================================
// Fused scan: 128 blocks x 512 threads = 2 chains of 256 (named bars).
// Per step: phase1 (hidden=relu(zW2^T+h2)), u-matvec (u=C s_t, fused,
// same mapping/tree as phase2), phase2 (z'=clip(zA + hW1^T + h1 + u)).
// s_t staged 2 steps ahead via LDG->smem ring. All weights (W2, W1, C)
// register-resident: 48 u64/lane. Conflict-free pad-swizzled smem.
// =====================================================================
#define ZST 36   // z: 8 chunks of 8 floats
#define HST 18   // hidden/s: 16 chunks of 8 floats

__global__ void __launch_bounds__(512, 1)
recur_kernel(const float* __restrict__ inp,  const float* __restrict__ Ag,
             const float* __restrict__ W1g,  const float* __restrict__ W2g,
             const float* __restrict__ h1g,  const float* __restrict__ h2g,
             const float* __restrict__ Cg,   const float* __restrict__ Woutg,
             const float* __restrict__ boutg, float* __restrict__ outg) {
    __shared__ __align__(16) float zbuf[2][8 * ZST];
    __shared__ __align__(16) float hbuf[2][16 * HST];
    __shared__ __align__(16) float sbuf[2][2][16 * HST];   // [gid][parity]

    const int tid = threadIdx.x;
    const int gid = tid >> 8;
    const int c   = tid & 255;
    const int bat = blockIdx.x * 2 + gid;
    const int barid = 1 + gid;

    // phase1 mapping: kc1 = z-chunk(8), rows 4*rg1..+3 of W2
    const int kc1 = c & 7;
    const int rg1 = c >> 3;
    const int b4a = (c >> 2) & 1;
    const int b2a = (c >> 1) & 1;
    const int hrow = 4 * rg1 + 2 * b4a + b2a;

    // phase2 + u mapping: kc2 = chunk(8), rows 4*rg2..+3 of W1 / C
    const int kc2 = c & 15;
    const int rg2 = c >> 4;
    const int b1b = c & 1;
    const int b2b = (c >> 1) & 1;
    const int lz  = 4 * rg2 + 2 * b1b + b2b;

    // register-resident weights: 16+16+16 u64 = 96 regs
    unsigned long long w2r[4][4];
    #pragma unroll
    for (int r = 0; r < 4; ++r)
        #pragma unroll
        for (int j = 0; j < 4; ++j)
            w2r[r][j] = *reinterpret_cast<const unsigned long long*>(
                &W2g[(4 * rg1 + r) * LAT + 8 * kc1 + 2 * j]);
    unsigned long long w1r[4][4];
    #pragma unroll
    for (int r = 0; r < 4; ++r)
        #pragma unroll
        for (int j = 0; j < 4; ++j)
            w1r[r][j] = *reinterpret_cast<const unsigned long long*>(
                &W1g[(4 * rg2 + r) * HID + 8 * kc2 + 2 * j]);
    unsigned long long cwr[4][4];
    #pragma unroll
    for (int r = 0; r < 4; ++r)
        #pragma unroll
        for (int j = 0; j < 4; ++j)
            cwr[r][j] = *reinterpret_cast<const unsigned long long*>(
                &Cg[(4 * rg2 + r) * INP + 8 * kc2 + 2 * j]);

    const float h2c = h2g[hrow];
    const float Ac  = Ag[lz];
    const float h1c = h1g[lz];

    // staging base for this lane (lanes c<64 stage s): float2 j=c
    const float* sgbase = inp + (size_t)bat * TT * INP + 2 * c;
    float* ssl0 = &sbuf[gid][0][(c >> 2) * HST + 2 * (c & 3)];
    float* ssl1 = &sbuf[gid][1][(c >> 2) * HST + 2 * (c & 3)];

    // prologue: zero z, stage s(0), s(1)
    if ((c & 12) == 0) zbuf[gid][(lz >> 3) * ZST + (lz & 7)] = 0.0f;
    if (c < 64) {
        *reinterpret_cast<float2*>(ssl0) =
            *reinterpret_cast<const float2*>(sgbase);
        *reinterpret_cast<float2*>(ssl1) =
            *reinterpret_cast<const float2*>(sgbase + INP);
    }
    __syncthreads();

    const float* zptr = &zbuf[gid][kc1 * ZST];
    const unsigned long long* hptr =
        reinterpret_cast<const unsigned long long*>(&hbuf[gid][kc2 * HST]);
    const unsigned long long* sptr0 =
        reinterpret_cast<const unsigned long long*>(&sbuf[gid][0][kc2 * HST]);
    const unsigned long long* sptr1 =
        reinterpret_cast<const unsigned long long*>(&sbuf[gid][1][kc2 * HST]);

    float zprev = 0.0f;
    const unsigned FULL = 0xffffffffu;

    for (int t = 0; t < TT; ++t) {
        // stage s(t+2) (clamped) -> registers now, smem after gbar1
        float2 sv = make_float2(0.f, 0.f);
        if (c < 64) {
            int tp2 = (t + 2 < TT) ? (t + 2) : (TT - 1);
            sv = *reinterpret_cast<const float2*>(sgbase + (size_t)tp2 * INP);
        }

        // ======== phase 1: hidden = relu(z @ W2^T + h2) ========
        float hval;
        {
            ulonglong2 za = *reinterpret_cast<const ulonglong2*>(zptr);
            ulonglong2 zb = *reinterpret_cast<const ulonglong2*>(zptr + 4);
            float p[4];
            #pragma unroll
            for (int r = 0; r < 4; ++r) {
                unsigned long long acc = 0ull;
                fma2(acc, za.x, w2r[r][0]);
                fma2(acc, za.y, w2r[r][1]);
                fma2(acc, zb.x, w2r[r][2]);
                fma2(acc, zb.y, w2r[r][3]);
                p[r] = psum2(acc);
            }
            float s0 = b4a ? p[0] : p[2];
            float r0 = __shfl_xor_sync(FULL, s0, 4);
            float s1 = b4a ? p[1] : p[3];
            float r1 = __shfl_xor_sync(FULL, s1, 4);
            float q0 = (b4a ? p[2] : p[0]) + r0;
            float q1 = (b4a ? p[3] : p[1]) + r1;
            float s2 = b2a ? q0 : q1;
            float r2 = __shfl_xor_sync(FULL, s2, 2);
            float s  = (b2a ? q1 : q0) + r2;
            s += __shfl_xor_sync(FULL, s, 1);
            hval = fmaxf(s + h2c, 0.0f);
        }

        // ======== u-matvec: u_t[lz] = C[lz] . s_t + h1  (overlaps bar) ====
        float u_t;
        {
            const unsigned long long* sp = (t & 1) ? sptr1 : sptr0;
            unsigned long long s0v = sp[0];
            unsigned long long s1v = sp[1];
            unsigned long long s2v = sp[2];
            unsigned long long s3v = sp[3];
            float p[4];
            #pragma unroll
            for (int r = 0; r < 4; ++r) {
                unsigned long long acc = 0ull;
                fma2(acc, s0v, cwr[r][0]);
                fma2(acc, s1v, cwr[r][1]);
                fma2(acc, s2v, cwr[r][2]);
                fma2(acc, s3v, cwr[r][3]);
                p[r] = psum2(acc);
            }
            float s0 = b1b ? p[0] : p[2];
            float r0 = __shfl_xor_sync(FULL, s0, 1);
            float s1 = b1b ? p[1] : p[3];
            float r1 = __shfl_xor_sync(FULL, s1, 1);
            float q0 = (b1b ? p[2] : p[0]) + r0;
            float q1 = (b1b ? p[3] : p[1]) + r1;
            float s2 = b2b ? q0 : q1;
            float r2 = __shfl_xor_sync(FULL, s2, 2);
            float v  = (b2b ? q1 : q0) + r2;
            v += __shfl_xor_sync(FULL, v, 4);
            v += __shfl_xor_sync(FULL, v, 8);
            u_t = v + h1c;
        }

        if (!(c & 1))
            hbuf[gid][(hrow >> 3) * HST + (hrow & 7)] = hval;
        gbar(barid);

        // publish s(t+2) into ring slot (t&1) — read again at step t+2
        if (c < 64)
            *reinterpret_cast<float2*>((t & 1) ? ssl1 : ssl0) = sv;

        // ======== phase 2: z' = clip(z*A + hidden @ W1^T + u_t) ========
        {
            unsigned long long h0 = hptr[0];
            unsigned long long h1v = hptr[1];
            unsigned long long h2v = hptr[2];
            unsigned long long h3v = hptr[3];
            float p[4];
            #pragma unroll
            for (int r = 0; r < 4; ++r) {
                unsigned long long acc = 0ull;
                fma2(acc, h0,  w1r[r][0]);
                fma2(acc, h1v, w1r[r][1]);
                fma2(acc, h2v, w1r[r][2]);
                fma2(acc, h3v, w1r[r][3]);
                p[r] = psum2(acc);
            }
            float s0 = b1b ? p[0] : p[2];
            float r0 = __shfl_xor_sync(FULL, s0, 1);
            float s1 = b1b ? p[1] : p[3];
            float r1 = __shfl_xor_sync(FULL, s1, 1);
            float q0 = (b1b ? p[2] : p[0]) + r0;
            float q1 = (b1b ? p[3] : p[1]) + r1;
            float s2 = b2b ? q0 : q1;
            float r2 = __shfl_xor_sync(FULL, s2, 2);
            float v  = (b2b ? q1 : q0) + r2;
            v += __shfl_xor_sync(FULL, v, 4);
            v += __shfl_xor_sync(FULL, v, 8);

            float zn = zprev * Ac + (v + u_t);
            zn = fminf(5.0f, fmaxf(-5.0f, zn));
            zprev = zn;
            if ((c & 12) == 0)
                zbuf[gid][(lz >> 3) * ZST + (lz & 7)] = zn;
        }
        gbar(barid);
    }

    // ---- epilogue: out[bat][o] = zT . Wout[o] + bout[o]
    if (c < OUTD) {
        const int o = c;
        float acc = boutg[o];
        #pragma unroll
        for (int l = 0; l < LAT; ++l)
            acc += zbuf[gid][(l >> 3) * ZST + (l & 7)] * Woutg[o * LAT + l];
        outg[(size_t)bat * OUTD + o] = acc;
    }
}

// =====================================================================
extern "C" void kernel_launch(void* const* d_in, const int* in_sizes, int n_in,
                              void* d_out, int out_size) {
    (void)in_sizes; (void)n_in; (void)out_size;
    const float* inp   = (const float*)d_in[0];
    const float* Ag    = (const float*)d_in[1];
    const float* W1g   = (const float*)d_in[2];
    const float* W2g   = (const float*)d_in[3];
    const float* h1g   = (const float*)d_in[4];
    const float* h2g   = (const float*)d_in[5];
    const float* Cg    = (const float*)d_in[6];
    const float* Woutg = (const float*)d_in[7];
    const float* boutg = (const float*)d_in[8];
    float* outg = (float*)d_out;

    recur_kernel<<<BATCH / 2, 512>>>(inp, Ag, W1g, W2g, h1g, h2g, Cg,
                                     Woutg, boutg, outg);
}

// round 10
// speedup vs baseline: 1.1294x; 1.1294x over previous
#include <cuda_runtime.h>
#include <cuda_fp16.h>

// Problem constants
#define BATCH 256
#define TT    1024
#define INP   128
#define LAT   64
#define HID   128
#define OUTD  32

// Scratch: drive[b][t][l] in fp16, 32 MB
__device__ __half g_drive_h[(size_t)BATCH * TT * LAT];

// ---------- f32x2 helpers ----------
__device__ __forceinline__ void fma2(unsigned long long& acc,
                                     unsigned long long a,
                                     unsigned long long b) {
    asm("fma.rn.f32x2 %0, %1, %2, %0;" : "+l"(acc) : "l"(a), "l"(b));
}
__device__ __forceinline__ float psum2(unsigned long long v) {
    float lo, hi;
    asm("mov.b64 {%0,%1}, %2;" : "=f"(lo), "=f"(hi) : "l"(v));
    return lo + hi;
}
__device__ __forceinline__ void gbar(int id) {
    asm volatile("bar.sync %0, 256;" :: "r"(id) : "memory");
}

// =====================================================================
// Kernel 1: drive = input @ C^T   [B*T,128] x [64,128]^T -> [B*T,64]
// 64-row tiles (66 KB smem) -> 3 blocks/SM for latency overlap.
// 128 threads, 4x8 thread tile, LDS.64 conflict-free. fp16 output.
// =====================================================================
#define AST 130

__global__ void __launch_bounds__(128, 3)
drive_kernel(const float* __restrict__ inp, const float* __restrict__ Cg) {
    extern __shared__ char smem1[];
    float* As = reinterpret_cast<float*>(smem1);                  // [64][130]
    float2* Cp = reinterpret_cast<float2*>(smem1 + 64 * AST * 4); // [64 jp][64 col_sw]

    const int tid = threadIdx.x;
    const int m0  = blockIdx.x * 64;

    // stage input tile: 64 rows x 128 floats at stride 130
    #pragma unroll
    for (int e = tid; e < 2048; e += 128) {
        int row = e >> 5;
        int q   = e & 31;
        float4 v = reinterpret_cast<const float4*>(inp + (size_t)(m0 + row) * INP)[q];
        float* dst = &As[row * AST + q * 4];
        *reinterpret_cast<float2*>(dst)     = make_float2(v.x, v.y);
        *reinterpret_cast<float2*>(dst + 2) = make_float2(v.z, v.w);
    }
    // stage C as k-pairs with swizzled col index: Cp[jp][ (col&7)*8 + col>>3 ]
    #pragma unroll
    for (int idx = tid; idx < 2048; idx += 128) {
        int col = idx >> 5;
        int q   = idx & 31;
        float4 v = reinterpret_cast<const float4*>(Cg)[idx];
        int csw = (col & 7) * 8 + (col >> 3);
        Cp[(2 * q) * 64 + csw]     = make_float2(v.x, v.y);
        Cp[(2 * q + 1) * 64 + csw] = make_float2(v.z, v.w);
    }
    __syncthreads();

    const int ctx = tid & 7;       // col group: cols ctx*8 .. ctx*8+7
    const int rt  = tid >> 3;      // row base: rows rt + 16k, k=0..3

    const unsigned long long* Cu = reinterpret_cast<const unsigned long long*>(Cp);

    unsigned long long acc[4][8];
    #pragma unroll
    for (int k = 0; k < 4; ++k)
        #pragma unroll
        for (int c = 0; c < 8; ++c) acc[k][c] = 0ull;

    #pragma unroll 4
    for (int jp = 0; jp < 64; ++jp) {
        unsigned long long cw[8];
        #pragma unroll
        for (int c = 0; c < 8; ++c)
            cw[c] = Cu[jp * 64 + c * 8 + ctx];
        unsigned long long av[4];
        #pragma unroll
        for (int k = 0; k < 4; ++k)
            av[k] = *reinterpret_cast<const unsigned long long*>(
                &As[(rt + 16 * k) * AST + 2 * jp]);
        #pragma unroll
        for (int k = 0; k < 4; ++k)
            #pragma unroll
            for (int c = 0; c < 8; ++c)
                fma2(acc[k][c], av[k], cw[c]);
    }

    // store 8 cols as fp16 -> one STG.128 per row
    #pragma unroll
    for (int k = 0; k < 4; ++k) {
        size_t row = (size_t)(m0 + rt + 16 * k);
        __half2 h0 = __floats2half2_rn(psum2(acc[k][0]), psum2(acc[k][1]));
        __half2 h1 = __floats2half2_rn(psum2(acc[k][2]), psum2(acc[k][3]));
        __half2 h2 = __floats2half2_rn(psum2(acc[k][4]), psum2(acc[k][5]));
        __half2 h3 = __floats2half2_rn(psum2(acc[k][6]), psum2(acc[k][7]));
        uint4 pack;
        pack.x = *reinterpret_cast<unsigned*>(&h0);
        pack.y = *reinterpret_cast<unsigned*>(&h1);
        pack.z = *reinterpret_cast<unsigned*>(&h2);
        pack.w = *reinterpret_cast<unsigned*>(&h3);
        *reinterpret_cast<uint4*>(&g_drive_h[row * LAT + ctx * 8]) = pack;
    }
}

// =====================================================================
// Kernel 2: scan (stable R7/R8 structure). 128 blocks x 512 threads.
// phase1: 4 rows x 8k (2 LDS.128, zbuf stride 36), depth-3 shfl tree
// phase2: 4 rows x 8k (4 LDS.64, hbuf stride 18), depth-4 shfl tree
// u loaded as fp16, h1 folded at prefetch.
// =====================================================================
#define ZST 36
#define HST 18

__global__ void __launch_bounds__(512, 1)
recur_kernel(const float* __restrict__ Ag,   const float* __restrict__ W1g,
             const float* __restrict__ W2g,  const float* __restrict__ h1g,
             const float* __restrict__ h2g,  const float* __restrict__ Woutg,
             const float* __restrict__ boutg, float* __restrict__ outg) {
    __shared__ __align__(16) float zbuf[2][8 * ZST];
    __shared__ __align__(16) float hbuf[2][16 * HST];

    const int tid = threadIdx.x;
    const int gid = tid >> 8;
    const int c   = tid & 255;
    const int bat = blockIdx.x * 2 + gid;
    const int barid = 1 + gid;

    // phase1 mapping
    const int kc1 = c & 7;
    const int rg1 = c >> 3;
    const int b4a = (c >> 2) & 1;
    const int b2a = (c >> 1) & 1;
    const int hrow = 4 * rg1 + 2 * b4a + b2a;

    // phase2 mapping
    const int kc2 = c & 15;
    const int rg2 = c >> 4;
    const int b1b = c & 1;
    const int b2b = (c >> 1) & 1;
    const int lz  = 4 * rg2 + 2 * b1b + b2b;

    unsigned long long w2r[4][4];
    #pragma unroll
    for (int r = 0; r < 4; ++r)
        #pragma unroll
        for (int j = 0; j < 4; ++j)
            w2r[r][j] = *reinterpret_cast<const unsigned long long*>(
                &W2g[(4 * rg1 + r) * LAT + 8 * kc1 + 2 * j]);
    unsigned long long w1r[4][4];
    #pragma unroll
    for (int r = 0; r < 4; ++r)
        #pragma unroll
        for (int j = 0; j < 4; ++j)
            w1r[r][j] = *reinterpret_cast<const unsigned long long*>(
                &W1g[(4 * rg2 + r) * HID + 8 * kc2 + 2 * j]);

    const float h2c = h2g[hrow];
    const float Ac  = Ag[lz];
    const float h1c = h1g[lz];

    if ((c & 12) == 0) zbuf[gid][(lz >> 3) * ZST + (lz & 7)] = 0.0f;
    __syncthreads();

    const float* zptr = &zbuf[gid][kc1 * ZST];
    const unsigned long long* hptr =
        reinterpret_cast<const unsigned long long*>(&hbuf[gid][kc2 * HST]);

    float zprev = 0.0f;
    const size_t ubase = ((size_t)bat) * TT * LAT + lz;
    float u_cur = __half2float(g_drive_h[ubase]) + h1c;
    float u_nxt = __half2float(g_drive_h[ubase + LAT]) + h1c;

    const unsigned FULL = 0xffffffffu;

    for (int t = 0; t < TT; ++t) {
        const int tp = (t + 2 < TT) ? (t + 2) : (TT - 1);
        float u_fut = __half2float(g_drive_h[ubase + (size_t)tp * LAT]) + h1c;

        // ======== phase 1: hidden = relu(z @ W2^T + h2) ========
        {
            ulonglong2 za = *reinterpret_cast<const ulonglong2*>(zptr);
            ulonglong2 zb = *reinterpret_cast<const ulonglong2*>(zptr + 4);
            float p[4];
            #pragma unroll
            for (int r = 0; r < 4; ++r) {
                unsigned long long acc = 0ull;
                fma2(acc, za.x, w2r[r][0]);
                fma2(acc, za.y, w2r[r][1]);
                fma2(acc, zb.x, w2r[r][2]);
                fma2(acc, zb.y, w2r[r][3]);
                p[r] = psum2(acc);
            }
            float s0 = b4a ? p[0] : p[2];
            float r0 = __shfl_xor_sync(FULL, s0, 4);
            float s1 = b4a ? p[1] : p[3];
            float r1 = __shfl_xor_sync(FULL, s1, 4);
            float q0 = (b4a ? p[2] : p[0]) + r0;
            float q1 = (b4a ? p[3] : p[1]) + r1;
            float s2 = b2a ? q0 : q1;
            float r2 = __shfl_xor_sync(FULL, s2, 2);
            float s  = (b2a ? q1 : q0) + r2;
            s += __shfl_xor_sync(FULL, s, 1);
            float hval = fmaxf(s + h2c, 0.0f);
            if (!(c & 1))
                hbuf[gid][(hrow >> 3) * HST + (hrow & 7)] = hval;
        }
        gbar(barid);

        // ======== phase 2: z' = clip(z*A + hidden @ W1^T + (h1+u)) ========
        {
            unsigned long long h0 = hptr[0];
            unsigned long long h1v = hptr[1];
            unsigned long long h2v = hptr[2];
            unsigned long long h3v = hptr[3];
            float p[4];
            #pragma unroll
            for (int r = 0; r < 4; ++r) {
                unsigned long long acc = 0ull;
                fma2(acc, h0,  w1r[r][0]);
                fma2(acc, h1v, w1r[r][1]);
                fma2(acc, h2v, w1r[r][2]);
                fma2(acc, h3v, w1r[r][3]);
                p[r] = psum2(acc);
            }
            float s0 = b1b ? p[0] : p[2];
            float r0 = __shfl_xor_sync(FULL, s0, 1);
            float s1 = b1b ? p[1] : p[3];
            float r1 = __shfl_xor_sync(FULL, s1, 1);
            float q0 = (b1b ? p[2] : p[0]) + r0;
            float q1 = (b1b ? p[3] : p[1]) + r1;
            float s2 = b2b ? q0 : q1;
            float r2 = __shfl_xor_sync(FULL, s2, 2);
            float v  = (b2b ? q1 : q0) + r2;
            v += __shfl_xor_sync(FULL, v, 4);
            v += __shfl_xor_sync(FULL, v, 8);

            float zn = zprev * Ac + (v + u_cur);
            zn = fminf(5.0f, fmaxf(-5.0f, zn));
            zprev = zn;
            if ((c & 12) == 0)
                zbuf[gid][(lz >> 3) * ZST + (lz & 7)] = zn;
        }
        u_cur = u_nxt;
        u_nxt = u_fut;
        gbar(barid);
    }

    // ---- epilogue: out[bat][o] = zT . Wout[o] + bout[o]
    if (c < OUTD) {
        const int o = c;
        float acc = boutg[o];
        #pragma unroll
        for (int l = 0; l < LAT; ++l)
            acc += zbuf[gid][(l >> 3) * ZST + (l & 7)] * Woutg[o * LAT + l];
        outg[(size_t)bat * OUTD + o] = acc;
    }
}

// =====================================================================
extern "C" void kernel_launch(void* const* d_in, const int* in_sizes, int n_in,
                              void* d_out, int out_size) {
    (void)in_sizes; (void)n_in; (void)out_size;
    const float* inp   = (const float*)d_in[0];
    const float* Ag    = (const float*)d_in[1];
    const float* W1g   = (const float*)d_in[2];
    const float* W2g   = (const float*)d_in[3];
    const float* h1g   = (const float*)d_in[4];
    const float* h2g   = (const float*)d_in[5];
    const float* Cg    = (const float*)d_in[6];
    const float* Woutg = (const float*)d_in[7];
    const float* boutg = (const float*)d_in[8];
    float* outg = (float*)d_out;

    const int smem1 = 64 * AST * 4 + 64 * 64 * 8; // 33280 + 32768 = 66048 B
    cudaFuncSetAttribute(drive_kernel, cudaFuncAttributeMaxDynamicSharedMemorySize, smem1);

    drive_kernel<<<(BATCH * TT) / 64, 128, smem1>>>(inp, Cg);
    recur_kernel<<<BATCH / 2, 512>>>(Ag, W1g, W2g, h1g, h2g, Woutg, boutg, outg);
}

// round 11
// speedup vs baseline: 1.2309x; 1.0899x over previous
#include <cuda_runtime.h>
#include <cuda_bf16.h>

// Problem constants
#define BATCH 256
#define TT    1024
#define INP   128
#define LAT   64
#define HID   128
#define OUTD  32

// Scratch: drive[b][t][l] (fp32), 64 MB
__device__ float g_drive[(size_t)BATCH * TT * LAT];

// ---------- f32x2 helpers ----------
__device__ __forceinline__ void fma2(unsigned long long& acc,
                                     unsigned long long a,
                                     unsigned long long b) {
    asm("fma.rn.f32x2 %0, %1, %2, %0;" : "+l"(acc) : "l"(a), "l"(b));
}
__device__ __forceinline__ float psum2(unsigned long long v) {
    float lo, hi;
    asm("mov.b64 {%0,%1}, %2;" : "=f"(lo), "=f"(hi) : "l"(v));
    return lo + hi;
}
__device__ __forceinline__ unsigned long long pack2(float lo, float hi) {
    unsigned long long r;
    asm("mov.b64 %0, {%1,%2};" : "=l"(r) : "f"(lo), "f"(hi));
    return r;
}
__device__ __forceinline__ void gbar(int id) {
    asm volatile("bar.sync %0, 256;" :: "r"(id) : "memory");
}

// =====================================================================
// Kernel 1: drive = input @ C^T   [B*T,128] x [64,128]^T -> [B*T,64]
// 128 threads, 8x8 thread tile, jp-PAIR inner loop: both operands via
// LDS.128 (half the LDS instruction count of R8; same wavefronts).
// AST=132 for 16B alignment; all loads conflict-free. 2 blocks/SM.
// =====================================================================
#define AST 132

__global__ void __launch_bounds__(128, 2)
drive_kernel(const float* __restrict__ inp, const float* __restrict__ Cg) {
    extern __shared__ char smem1[];
    float* As = reinterpret_cast<float*>(smem1);                       // [128][132]
    ulonglong2* Cq = reinterpret_cast<ulonglong2*>(smem1 + 128 * AST * 4); // [32 q][64 csw]

    const int tid = threadIdx.x;
    const int m0  = blockIdx.x * 128;

    // stage input tile: 128 rows x 128 floats at stride 132
    #pragma unroll
    for (int e = tid; e < 4096; e += 128) {
        int row = e >> 5;
        int q4  = e & 31;
        float4 v = reinterpret_cast<const float4*>(inp + (size_t)(m0 + row) * INP)[q4];
        *reinterpret_cast<float4*>(&As[row * AST + q4 * 4]) = v;
    }
    // stage C as jp-pairs: Cq[q][(col&7)*8 + col>>3] = {(c0,c1),(c2,c3)} of C[col][4q..4q+3]
    #pragma unroll
    for (int idx = tid; idx < 2048; idx += 128) {
        int col = idx >> 5;
        int q4  = idx & 31;
        float4 v = reinterpret_cast<const float4*>(Cg)[idx];
        int csw = (col & 7) * 8 + (col >> 3);
        ulonglong2 p;
        p.x = pack2(v.x, v.y);
        p.y = pack2(v.z, v.w);
        Cq[q4 * 64 + csw] = p;
    }
    __syncthreads();

    const int ctx = tid & 7;       // col group: cols ctx*8 .. ctx*8+7
    const int rt  = tid >> 3;      // row base: rows rt + 16k, k=0..7

    unsigned long long acc[8][8];
    #pragma unroll
    for (int k = 0; k < 8; ++k)
        #pragma unroll
        for (int c = 0; c < 8; ++c) acc[k][c] = 0ull;

    #pragma unroll 4
    for (int q = 0; q < 32; ++q) {     // q = jp pair (covers k 4q..4q+3)
        ulonglong2 cw[8];
        #pragma unroll
        for (int c = 0; c < 8; ++c)
            cw[c] = Cq[q * 64 + c * 8 + ctx];
        ulonglong2 av[8];
        #pragma unroll
        for (int k = 0; k < 8; ++k)
            av[k] = *reinterpret_cast<const ulonglong2*>(&As[(rt + 16 * k) * AST + 4 * q]);
        #pragma unroll
        for (int k = 0; k < 8; ++k)
            #pragma unroll
            for (int c = 0; c < 8; ++c) {
                fma2(acc[k][c], av[k].x, cw[c].x);
                fma2(acc[k][c], av[k].y, cw[c].y);
            }
    }

    // cols ctx*8 + c contiguous -> 2x STG.128 per row
    #pragma unroll
    for (int k = 0; k < 8; ++k) {
        size_t row = (size_t)(m0 + rt + 16 * k);
        float4 o0, o1;
        o0.x = psum2(acc[k][0]); o0.y = psum2(acc[k][1]);
        o0.z = psum2(acc[k][2]); o0.w = psum2(acc[k][3]);
        o1.x = psum2(acc[k][4]); o1.y = psum2(acc[k][5]);
        o1.z = psum2(acc[k][6]); o1.w = psum2(acc[k][7]);
        float* dst = &g_drive[row * LAT + ctx * 8];
        reinterpret_cast<float4*>(dst)[0] = o0;
        reinterpret_cast<float4*>(dst)[1] = o1;
    }
}

// =====================================================================
// Kernel 2: scan (best-known R7/R8 structure, fp32 u). 128 x 512.
// phase1: 4 rows x 8k (2 LDS.128, zbuf stride 36), depth-3 shfl tree
// phase2: 4 rows x 8k (4 LDS.64, hbuf stride 18), depth-4 shfl tree
// h1 folded into u at prefetch.
// =====================================================================
#define ZST 36
#define HST 18

__global__ void __launch_bounds__(512, 1)
recur_kernel(const float* __restrict__ Ag,   const float* __restrict__ W1g,
             const float* __restrict__ W2g,  const float* __restrict__ h1g,
             const float* __restrict__ h2g,  const float* __restrict__ Woutg,
             const float* __restrict__ boutg, float* __restrict__ outg) {
    __shared__ __align__(16) float zbuf[2][8 * ZST];
    __shared__ __align__(16) float hbuf[2][16 * HST];

    const int tid = threadIdx.x;
    const int gid = tid >> 8;
    const int c   = tid & 255;
    const int bat = blockIdx.x * 2 + gid;
    const int barid = 1 + gid;

    // phase1 mapping
    const int kc1 = c & 7;
    const int rg1 = c >> 3;
    const int b4a = (c >> 2) & 1;
    const int b2a = (c >> 1) & 1;
    const int hrow = 4 * rg1 + 2 * b4a + b2a;

    // phase2 mapping
    const int kc2 = c & 15;
    const int rg2 = c >> 4;
    const int b1b = c & 1;
    const int b2b = (c >> 1) & 1;
    const int lz  = 4 * rg2 + 2 * b1b + b2b;

    unsigned long long w2r[4][4];
    #pragma unroll
    for (int r = 0; r < 4; ++r)
        #pragma unroll
        for (int j = 0; j < 4; ++j)
            w2r[r][j] = *reinterpret_cast<const unsigned long long*>(
                &W2g[(4 * rg1 + r) * LAT + 8 * kc1 + 2 * j]);
    unsigned long long w1r[4][4];
    #pragma unroll
    for (int r = 0; r < 4; ++r)
        #pragma unroll
        for (int j = 0; j < 4; ++j)
            w1r[r][j] = *reinterpret_cast<const unsigned long long*>(
                &W1g[(4 * rg2 + r) * HID + 8 * kc2 + 2 * j]);

    const float h2c = h2g[hrow];
    const float Ac  = Ag[lz];
    const float h1c = h1g[lz];

    if ((c & 12) == 0) zbuf[gid][(lz >> 3) * ZST + (lz & 7)] = 0.0f;
    __syncthreads();

    const float* zptr = &zbuf[gid][kc1 * ZST];
    const unsigned long long* hptr =
        reinterpret_cast<const unsigned long long*>(&hbuf[gid][kc2 * HST]);

    float zprev = 0.0f;
    const size_t ubase = ((size_t)bat) * TT * LAT + lz;
    float u_cur = g_drive[ubase] + h1c;
    float u_nxt = g_drive[ubase + LAT] + h1c;

    const unsigned FULL = 0xffffffffu;

    for (int t = 0; t < TT; ++t) {
        const int tp = (t + 2 < TT) ? (t + 2) : (TT - 1);
        float u_fut = g_drive[ubase + (size_t)tp * LAT] + h1c;

        // ======== phase 1: hidden = relu(z @ W2^T + h2) ========
        {
            ulonglong2 za = *reinterpret_cast<const ulonglong2*>(zptr);
            ulonglong2 zb = *reinterpret_cast<const ulonglong2*>(zptr + 4);
            float p[4];
            #pragma unroll
            for (int r = 0; r < 4; ++r) {
                unsigned long long acc = 0ull;
                fma2(acc, za.x, w2r[r][0]);
                fma2(acc, za.y, w2r[r][1]);
                fma2(acc, zb.x, w2r[r][2]);
                fma2(acc, zb.y, w2r[r][3]);
                p[r] = psum2(acc);
            }
            float s0 = b4a ? p[0] : p[2];
            float r0 = __shfl_xor_sync(FULL, s0, 4);
            float s1 = b4a ? p[1] : p[3];
            float r1 = __shfl_xor_sync(FULL, s1, 4);
            float q0 = (b4a ? p[2] : p[0]) + r0;
            float q1 = (b4a ? p[3] : p[1]) + r1;
            float s2 = b2a ? q0 : q1;
            float r2 = __shfl_xor_sync(FULL, s2, 2);
            float s  = (b2a ? q1 : q0) + r2;
            s += __shfl_xor_sync(FULL, s, 1);
            float hval = fmaxf(s + h2c, 0.0f);
            if (!(c & 1))
                hbuf[gid][(hrow >> 3) * HST + (hrow & 7)] = hval;
        }
        gbar(barid);

        // ======== phase 2: z' = clip(z*A + hidden @ W1^T + (h1+u)) ========
        {
            unsigned long long h0 = hptr[0];
            unsigned long long h1v = hptr[1];
            unsigned long long h2v = hptr[2];
            unsigned long long h3v = hptr[3];
            float p[4];
            #pragma unroll
            for (int r = 0; r < 4; ++r) {
                unsigned long long acc = 0ull;
                fma2(acc, h0,  w1r[r][0]);
                fma2(acc, h1v, w1r[r][1]);
                fma2(acc, h2v, w1r[r][2]);
                fma2(acc, h3v, w1r[r][3]);
                p[r] = psum2(acc);
            }
            float s0 = b1b ? p[0] : p[2];
            float r0 = __shfl_xor_sync(FULL, s0, 1);
            float s1 = b1b ? p[1] : p[3];
            float r1 = __shfl_xor_sync(FULL, s1, 1);
            float q0 = (b1b ? p[2] : p[0]) + r0;
            float q1 = (b1b ? p[3] : p[1]) + r1;
            float s2 = b2b ? q0 : q1;
            float r2 = __shfl_xor_sync(FULL, s2, 2);
            float v  = (b2b ? q1 : q0) + r2;
            v += __shfl_xor_sync(FULL, v, 4);
            v += __shfl_xor_sync(FULL, v, 8);

            float zn = zprev * Ac + (v + u_cur);
            zn = fminf(5.0f, fmaxf(-5.0f, zn));
            zprev = zn;
            if ((c & 12) == 0)
                zbuf[gid][(lz >> 3) * ZST + (lz & 7)] = zn;
        }
        u_cur = u_nxt;
        u_nxt = u_fut;
        gbar(barid);
    }

    // ---- epilogue: out[bat][o] = zT . Wout[o] + bout[o]
    if (c < OUTD) {
        const int o = c;
        float acc = boutg[o];
        #pragma unroll
        for (int l = 0; l < LAT; ++l)
            acc += zbuf[gid][(l >> 3) * ZST + (l & 7)] * Woutg[o * LAT + l];
        outg[(size_t)bat * OUTD + o] = acc;
    }
}

// =====================================================================
extern "C" void kernel_launch(void* const* d_in, const int* in_sizes, int n_in,
                              void* d_out, int out_size) {
    (void)in_sizes; (void)n_in; (void)out_size;
    const float* inp   = (const float*)d_in[0];
    const float* Ag    = (const float*)d_in[1];
    const float* W1g   = (const float*)d_in[2];
    const float* W2g   = (const float*)d_in[3];
    const float* h1g   = (const float*)d_in[4];
    const float* h2g   = (const float*)d_in[5];
    const float* Cg    = (const float*)d_in[6];
    const float* Woutg = (const float*)d_in[7];
    const float* boutg = (const float*)d_in[8];
    float* outg = (float*)d_out;

    const int smem1 = 128 * AST * 4 + 32 * 64 * 16; // 67584 + 32768 = 100352 B
    cudaFuncSetAttribute(drive_kernel, cudaFuncAttributeMaxDynamicSharedMemorySize, smem1);

    drive_kernel<<<(BATCH * TT) / 128, 128, smem1>>>(inp, Cg);
    recur_kernel<<<BATCH / 2, 512>>>(Ag, W1g, W2g, h1g, h2g, Woutg, boutg, outg);
}